// round 17
// baseline (speedup 1.0000x reference)
#include <cuda_runtime.h>
#include <cuda_fp16.h>
#include <cstdint>

// Problem constants
#define NE 8
#define ND 1024
#define NF 4096
#define NT 8192
#define NC 2048
#define NM (NE * NC)   // 16384 rows through the expert FFN

// ---------------- scratch (device globals; no runtime allocation) ----------
__device__ float g_scoresT[NE * NT];              // gates^T  [E, T]
__device__ int   g_idx[NM];                       // selected token ids [E*C]
__device__ float g_vals[NM];                      // routing probs of selected
__device__ __half g_xh[(size_t)NT * ND];          // x fp16
__device__ __half g_w1h[(size_t)NE * ND * NF];    // W1 fp16
__device__ __half g_w2h[(size_t)NE * NF * ND];    // W2 fp16
__device__ __half g_hh[(size_t)NM * NF];          // gelu output fp16

// ---------------- init output ------------------------------------------------
__global__ void init_out_kernel(float* out, size_t n_main, size_t total) {
    size_t i = (size_t)blockIdx.x * blockDim.x + threadIdx.x;
    size_t stride = (size_t)gridDim.x * blockDim.x;
    for (; i < total; i += stride) {
        if (i < n_main)       out[i] = 0.0f;
        else if (i == n_main) out[i] = 2.0f;   // aux_loss = E*(C/T)*1 = 2 analytically
        else                  out[i] = 0.0f;
    }
}

// ---------------- fp32 -> fp16 convert, 8 floats/thread ---------------------
__global__ void cvt_f16_kernel(const float4* __restrict__ in,
                               uint4* __restrict__ hi, size_t n8) {
    size_t i = (size_t)blockIdx.x * blockDim.x + threadIdx.x;
    if (i >= n8) return;
    float4 a = in[2 * i];
    float4 b = in[2 * i + 1];
    __half2 h[4];
    h[0] = __floats2half2_rn(a.x, a.y);
    h[1] = __floats2half2_rn(a.z, a.w);
    h[2] = __floats2half2_rn(b.x, b.y);
    h[3] = __floats2half2_rn(b.z, b.w);
    hi[i] = *(const uint4*)h;
}

// ---------------- router: gates = softmax(x @ Wg), stored transposed --------
__global__ void router_kernel(const float* __restrict__ x,
                              const float* __restrict__ Wg) {
    int warp = (blockIdx.x * blockDim.x + threadIdx.x) >> 5;
    int lane = threadIdx.x & 31;
    if (warp >= NT) return;
    const float* xr = x + (size_t)warp * ND;
    float acc[NE];
#pragma unroll
    for (int e = 0; e < NE; e++) acc[e] = 0.0f;
    for (int d = lane; d < ND; d += 32) {
        float xv = xr[d];
        const float4 w0 = *(const float4*)(Wg + d * NE);
        const float4 w1 = *(const float4*)(Wg + d * NE + 4);
        acc[0] += xv * w0.x; acc[1] += xv * w0.y;
        acc[2] += xv * w0.z; acc[3] += xv * w0.w;
        acc[4] += xv * w1.x; acc[5] += xv * w1.y;
        acc[6] += xv * w1.z; acc[7] += xv * w1.w;
    }
#pragma unroll
    for (int off = 16; off > 0; off >>= 1) {
#pragma unroll
        for (int e = 0; e < NE; e++)
            acc[e] += __shfl_down_sync(0xffffffffu, acc[e], off);
    }
    if (lane == 0) {
        float m = acc[0];
#pragma unroll
        for (int e = 1; e < NE; e++) m = fmaxf(m, acc[e]);
        float s = 0.0f;
#pragma unroll
        for (int e = 0; e < NE; e++) { acc[e] = expf(acc[e] - m); s += acc[e]; }
        float inv = 1.0f / s;
#pragma unroll
        for (int e = 0; e < NE; e++) g_scoresT[e * NT + warp] = acc[e] * inv;
    }
}

// ---------------- exact top-C per expert via 4-pass radix select ------------
__global__ void topk_kernel() {
    int e = blockIdx.x;
    int tid = threadIdx.x;
    const float* s = g_scoresT + e * NT;

    __shared__ unsigned hist[256];
    __shared__ unsigned sh_prefix;
    __shared__ int sh_rem;

    unsigned prefix = 0;
    int remaining = NC;

    for (int shift = 24; shift >= 0; shift -= 8) {
        if (tid < 256) hist[tid] = 0;
        __syncthreads();
        unsigned mask = (shift == 24) ? 0u : (0xFFFFFFFFu << (shift + 8));
        for (int t = tid; t < NT; t += blockDim.x) {
            unsigned k = __float_as_uint(s[t]);
            if ((k & mask) == prefix) atomicAdd(&hist[(k >> shift) & 0xFFu], 1u);
        }
        __syncthreads();
        if (tid == 0) {
            int rem = remaining;
            int b = 0;
            for (int d = 255; d >= 0; d--) {
                int h = (int)hist[d];
                if (h >= rem) { b = d; break; }
                rem -= h;
            }
            sh_prefix = prefix | ((unsigned)b << shift);
            sh_rem = rem;
        }
        __syncthreads();
        prefix = sh_prefix;
        remaining = sh_rem;
        __syncthreads();
    }

    __shared__ int cnt_gt, cnt_eq;
    if (tid == 0) { cnt_gt = 0; cnt_eq = 0; }
    __syncthreads();
    int base = NC - remaining;
    for (int t = tid; t < NT; t += blockDim.x) {
        unsigned k = __float_as_uint(s[t]);
        if (k > prefix) {
            int p = atomicAdd(&cnt_gt, 1);
            g_idx[e * NC + p]  = t;
            g_vals[e * NC + p] = s[t];
        } else if (k == prefix) {
            int p = atomicAdd(&cnt_eq, 1);
            if (p < remaining) {
                g_idx[e * NC + base + p]  = t;
                g_vals[e * NC + base + p] = s[t];
            }
        }
    }
}

// ---------------- gelu (tanh approx via fast exp; matches jax to ~1e-6) -----
__device__ __forceinline__ float gelu_f(float v) {
    float u = 0.7978845608028654f * (v + 0.044715f * v * v * v);
    float t = 1.0f - 2.0f / (__expf(2.0f * u) + 1.0f);
    return 0.5f * v * (1.0f + t);
}

// ============================ fp16 mma.sync GEMM ==============================
// CTA tile 128(M) x 128(N) x 64(K). 128 threads, 4 warps 2(m) x 2(n),
// warp tile 64x64 (ldsm:MMA = 0.5 -> halves smem crossbar traffic).
// Plain fp16 MMA, fp32 accum. 3-stage cp.async pipeline, single top barrier,
// 2 CTAs/SM.

static constexpr int A_STRIDE = 72;                 // 16-bit units (144 B, 9*16)
static constexpr int A_PLANE  = 128 * A_STRIDE;     // 9216
static constexpr int B_BASE   = 3 * A_PLANE;        // 27648
static constexpr int B_STRIDE = 136;                // 16-bit units (272 B, 17*16)
static constexpr int B_PLANE  = 64 * B_STRIDE;      // 8704
static constexpr int SMEM_U16 = B_BASE + 3 * B_PLANE;        // 53760
static constexpr int GEMM_SMEM_BYTES = SMEM_U16 * 2;         // 107520

__device__ __forceinline__ uint32_t smem_u32(const void* p) {
    uint32_t a;
    asm("{ .reg .u64 t; cvta.to.shared.u64 t, %1; cvt.u32.u64 %0, t; }"
        : "=r"(a) : "l"(p));
    return a;
}

__device__ __forceinline__ void cp16(uint32_t dst, const void* src) {
    asm volatile("cp.async.cg.shared.global [%0], [%1], 16;"
                 :: "r"(dst), "l"(src) : "memory");
}
#define CP_COMMIT() asm volatile("cp.async.commit_group;" ::: "memory")
#define CP_WAIT1()  asm volatile("cp.async.wait_group 1;" ::: "memory")

__device__ __forceinline__ void ldsm4(uint32_t* r, uint32_t addr) {
    asm volatile("ldmatrix.sync.aligned.m8n8.x4.shared.b16 {%0,%1,%2,%3}, [%4];"
                 : "=r"(r[0]), "=r"(r[1]), "=r"(r[2]), "=r"(r[3]) : "r"(addr));
}
__device__ __forceinline__ void ldsm4t(uint32_t* r, uint32_t addr) {
    asm volatile("ldmatrix.sync.aligned.m8n8.x4.trans.shared.b16 {%0,%1,%2,%3}, [%4];"
                 : "=r"(r[0]), "=r"(r[1]), "=r"(r[2]), "=r"(r[3]) : "r"(addr));
}

__device__ __forceinline__ void mma_f16(float* d, const uint32_t* a,
                                        const uint32_t* b) {
    asm volatile(
        "mma.sync.aligned.m16n8k16.row.col.f32.f16.f16.f32 "
        "{%0,%1,%2,%3}, {%4,%5,%6,%7}, {%8,%9}, {%0,%1,%2,%3};"
        : "+f"(d[0]), "+f"(d[1]), "+f"(d[2]), "+f"(d[3])
        : "r"(a[0]), "r"(a[1]), "r"(a[2]), "r"(a[3]), "r"(b[0]), "r"(b[1]));
}

__device__ __forceinline__ void red_v2(float* ptr, float v0, float v1) {
    asm volatile("red.global.add.v2.f32 [%0], {%1, %2};"
                 :: "l"(ptr), "f"(v0), "f"(v1) : "memory");
}

// NCH chunks of K=64 per CTA per K-slice. GATHER: A rows via g_idx (lda=ND).
// GELU_EPI: write fp16 gelu(acc+bias); else scatter-add into fp32 outa.
// blockIdx.z = K-slice; slice 0 adds bias. Ktot = full K (B expert stride).
template<int NCH, bool GATHER, bool GELU_EPI>
__global__ __launch_bounds__(128, 2) void gemm_tc_kernel(
    const uint16_t* __restrict__ Ah,
    const uint16_t* __restrict__ Bh,
    const float* __restrict__ bias,
    float* __restrict__ outa,
    __half* __restrict__ outbh,
    int Nld, int lda, int Ktot) {
    extern __shared__ __align__(16) uint16_t sm[];
    __shared__ int   tok_s[128];
    __shared__ float val_s[128];

    const int tid = threadIdx.x;
    const int warp = tid >> 5;
    const int lane = tid & 31;
    const int wm = warp >> 1;          // 0..1  (64-row slab)
    const int wn = warp & 1;           // 0..1  (64-col slab)
    const int r = lane >> 2;           // 0..7 (accumulator row)
    const int c = lane & 3;            // 0..3 (accumulator col pair)
    const int quad = lane >> 3;        // 0..3 (ldmatrix matrix id)
    const int r8 = lane & 7;           // row within 8x8 matrix

    const int n0 = blockIdx.x * 128;
    const int m0 = blockIdx.y * 128;
    const int e = m0 >> 11;            // m0 / NC
    const int kbase = blockIdx.z * NCH * 64;
    const bool bias_en = (blockIdx.z == 0);

    tok_s[tid] = g_idx[m0 + tid];
    val_s[tid] = g_vals[m0 + tid];
    __syncthreads();

    const uint32_t sbase = smem_u32(sm);

    // ---- precomputed load pointers (advance one K-chunk per load_stage) ----
    // A: 128 rows x 8 segs = 1024 cp16 -> 8 per thread. seg = (tid&7)*8 const,
    //    row_i = (tid>>3) + 16*i  (gathered rows need per-i pointers).
    // B: 64 rows x 16 segs = 1024 cp16 -> 8 per thread. seg = (tid&15)*8
    //    const, row_i = (tid>>4) + 8*i  (regular: one pointer + stride).
    const uint16_t* asrc[8];
    uint32_t adst0;
    const uint16_t* bsrc0;
    uint32_t bdst0;
    {
        const int arow0 = tid >> 3;
        const int aseg = (tid & 7) * 8;
#pragma unroll
        for (int i = 0; i < 8; i++) {
            int row = arow0 + 16 * i;
            asrc[i] = GATHER
                ? (Ah + (size_t)tok_s[row] * lda + kbase + aseg)
                : (Ah + (size_t)(m0 + row) * lda + kbase + aseg);
        }
        adst0 = sbase + (uint32_t)(arow0 * A_STRIDE + aseg) * 2;

        const int brow0 = tid >> 4;
        const int bseg = (tid & 15) * 8;
        bsrc0 = Bh + (size_t)e * Ktot * Nld + n0 +
                (size_t)(kbase + brow0) * Nld + bseg;
        bdst0 = sbase + (uint32_t)(B_BASE + brow0 * B_STRIDE + bseg) * 2;
    }

    auto load_stage = [&](int s) {
        const uint32_t ao = adst0 + (uint32_t)s * (A_PLANE * 2);
        const uint32_t bo = bdst0 + (uint32_t)s * (B_PLANE * 2);
#pragma unroll
        for (int j = 0; j < 8; j++) {
            cp16(ao + (uint32_t)(j * 16 * A_STRIDE) * 2, asrc[j]);
            asrc[j] += 64;
        }
        const uint16_t* bs = bsrc0;
#pragma unroll
        for (int j = 0; j < 8; j++) {
            cp16(bo + (uint32_t)(j * 8 * B_STRIDE) * 2, bs);
            bs += (size_t)8 * Nld;
        }
        bsrc0 += (size_t)64 * Nld;
    };

    float acc[4][8][4];                // [mt][nt][frag]
#pragma unroll
    for (int mt = 0; mt < 4; mt++)
#pragma unroll
        for (int nt = 0; nt < 8; nt++)
#pragma unroll
            for (int i = 0; i < 4; i++) acc[mt][nt][i] = 0.0f;

    // prologue: fill stages 0, 1 (prefetch distance 2)
    load_stage(0);
    CP_COMMIT();
    load_stage(1);
    CP_COMMIT();

    int s = 0;                         // current stage, wraps mod 3
    int sload = 2;                     // stage to load next, wraps mod 3
#pragma unroll 1
    for (int ch = 0; ch < NCH; ch++) {
        CP_WAIT1();
        __syncthreads();               // single barrier: also guards stage reuse
        if (ch + 2 < NCH) load_stage(sload);
        CP_COMMIT();   // unconditional: keeps wait_group bookkeeping exact

        const uint32_t sa = sbase + (uint32_t)s * (A_PLANE * 2);
        const uint32_t sb = sbase + (uint32_t)(B_BASE * 2 + s * (B_PLANE * 2));
#pragma unroll
        for (int ks = 0; ks < 4; ks++) {
            // ---- A fragments: 4 m-tiles via ldmatrix.x4 ----
            uint32_t ah[4][4];
            {
                const int m_local = wm * 64 + (quad & 1) * 8 + r8;
                const int k_off = ks * 16 + (quad >> 1) * 8;
                const uint32_t abase = sa +
                    (uint32_t)(m_local * A_STRIDE + k_off) * 2;
#pragma unroll
                for (int mt = 0; mt < 4; mt++)
                    ldsm4(ah[mt], abase + (uint32_t)(mt * 16 * A_STRIDE) * 2);
            }
            // ---- B fragments per 16-col group (4 groups = 64 cols) ----
            {
                const int k_row = ks * 16 + (quad & 1) * 8 + r8;
                const int n_col = wn * 64 + (quad >> 1) * 8;
                const uint32_t bbase = sb +
                    (uint32_t)(k_row * B_STRIDE + n_col) * 2;
#pragma unroll
                for (int nt2 = 0; nt2 < 4; nt2++) {
                    uint32_t bh[4];
                    ldsm4t(bh, bbase + (uint32_t)(nt2 * 16) * 2);
                    const int nt = nt2 * 2;
#pragma unroll
                    for (int mt = 0; mt < 4; mt++) {
                        mma_f16(acc[mt][nt],     ah[mt], bh);
                        mma_f16(acc[mt][nt + 1], ah[mt], bh + 2);
                    }
                }
            }
        }
        s = (s == 2) ? 0 : s + 1;
        sload = (sload == 2) ? 0 : sload + 1;
    }

    // ---------------- epilogue -----------------------------------------------
#pragma unroll
    for (int mt = 0; mt < 4; mt++) {
        const int lm0 = wm * 64 + mt * 16 + r;       // local row of acc[0],acc[1]
        const int lm1 = lm0 + 8;                     // local row of acc[2],acc[3]
#pragma unroll
        for (int nt = 0; nt < 8; nt++) {
            const int bcol = n0 + wn * 64 + nt * 8 + c * 2;
            const float bb0 = bias_en ? bias[e * Nld + bcol] : 0.0f;
            const float bb1 = bias_en ? bias[e * Nld + bcol + 1] : 0.0f;
            if (GELU_EPI) {
                __half2 hp0 = __floats2half2_rn(gelu_f(acc[mt][nt][0] + bb0),
                                                gelu_f(acc[mt][nt][1] + bb1));
                __half2 hp1 = __floats2half2_rn(gelu_f(acc[mt][nt][2] + bb0),
                                                gelu_f(acc[mt][nt][3] + bb1));
                *(__half2*)(outbh + (size_t)(m0 + lm0) * Nld + bcol) = hp0;
                *(__half2*)(outbh + (size_t)(m0 + lm1) * Nld + bcol) = hp1;
            } else {
                const float w0 = val_s[lm0];
                const float w1 = val_s[lm1];
                float* p0 = outa + (size_t)tok_s[lm0] * ND + bcol;
                float* p1 = outa + (size_t)tok_s[lm1] * ND + bcol;
                red_v2(p0, (acc[mt][nt][0] + bb0) * w0, (acc[mt][nt][1] + bb1) * w0);
                red_v2(p1, (acc[mt][nt][2] + bb0) * w1, (acc[mt][nt][3] + bb1) * w1);
            }
        }
    }
}

// ============================ host launch =====================================
extern "C" void kernel_launch(void* const* d_in, const int* in_sizes, int n_in,
                              void* d_out, int out_size) {
    const float* x  = (const float*)d_in[0];   // [T, D]
    const float* Wg = (const float*)d_in[1];   // [D, E]
    const float* W1 = (const float*)d_in[2];   // [E, D, F]
    const float* b1 = (const float*)d_in[3];   // [E, F]
    const float* W2 = (const float*)d_in[4];   // [E, F, D]
    const float* b2 = (const float*)d_in[5];   // [E, D]
    float* out = (float*)d_out;

    void *p_xh, *p_w1h, *p_w2h, *p_hh;
    cudaGetSymbolAddress(&p_xh, g_xh);
    cudaGetSymbolAddress(&p_w1h, g_w1h);
    cudaGetSymbolAddress(&p_w2h, g_w2h);
    cudaGetSymbolAddress(&p_hh, g_hh);

    cudaFuncSetAttribute(
        (const void*)gemm_tc_kernel<16, true, true>,
        cudaFuncAttributeMaxDynamicSharedMemorySize, GEMM_SMEM_BYTES);
    cudaFuncSetAttribute(
        (const void*)gemm_tc_kernel<32, false, false>,
        cudaFuncAttributeMaxDynamicSharedMemorySize, GEMM_SMEM_BYTES);

    size_t n_main = (size_t)NT * ND;
    init_out_kernel<<<512, 256>>>(out, n_main, (size_t)out_size);
    router_kernel<<<NT / 32, 1024>>>(x, Wg);
    topk_kernel<<<NE, 1024>>>();

    // Convert operands to fp16.
    cvt_f16_kernel<<<(NT * ND / 8 + 255) / 256, 256>>>(
        (const float4*)x, (uint4*)p_xh, (size_t)NT * ND / 8);
    cvt_f16_kernel<<<((size_t)NE * ND * NF / 8 + 255) / 256, 256>>>(
        (const float4*)W1, (uint4*)p_w1h, (size_t)NE * ND * NF / 8);
    cvt_f16_kernel<<<((size_t)NE * NF * ND / 8 + 255) / 256, 256>>>(
        (const float4*)W2, (uint4*)p_w2h, (size_t)NE * NF * ND / 8);

    // GEMM1: h = gelu(x[idx] @ W1[e] + b1[e])   fp16, K-chunk 64, 16 chunks
    gemm_tc_kernel<16, true, true>
        <<<dim3(NF / 128, NM / 128, 1), 128, GEMM_SMEM_BYTES>>>(
            (const uint16_t*)p_xh, (const uint16_t*)p_w1h,
            b1, nullptr, (__half*)p_hh, NF, ND, ND);

    // GEMM2: out[tok] += val*(h @ W2[e] + b2[e])   fp16, split-K=2, 32 chunks
    gemm_tc_kernel<32, false, false>
        <<<dim3(ND / 128, NM / 128, 2), 128, GEMM_SMEM_BYTES>>>(
            (const uint16_t*)p_hh, (const uint16_t*)p_w2h,
            b2, out, nullptr, ND, NF, NF);
}